// round 14
// baseline (speedup 1.0000x reference)
#include <cuda_runtime.h>
#include <math.h>

#define FULLMASK 0xffffffffu

#define BB 2
#define KK 2048
#define NN 16384
#define SROWS 65536      // B*K*16 sample-rows
#define ROWS 4096        // B*K
#define CBEV 256
#define HBEV 100
#define WBEV 176
#define FEAT_DIM 304
#define OUTC 128

// spatial hash for ball query
#define NXC 89
#define NYC 51
#define NCELL (NXC * NYC)    // 4539 per batch
#define CAP 64

// ---------------- scratch (device globals; no allocs allowed) ----------------
__device__ float4 g_g0[SROWS];            // grouped scale0: (rel xyz, feat)
__device__ float4 g_g1[SROWS];            // grouped scale1
__device__ unsigned char g_e0[ROWS];
__device__ unsigned char g_e1[ROWS];
__device__ float4 g_z0[SROWS * 4];        // scale0 layer1 pre-BN output (16 ch)
__device__ float4 g_z1[SROWS * 8];        // scale1 layer1 pre-BN output (32 ch)
__device__ float g_feats[ROWS * FEAT_DIM];
__device__ float g_fz[ROWS * OUTC];
// one zeroed region: [0:512) acc floats; [512:512+2*NCELL) ccnt ints
__device__ float g_zr[512 + 2 * NCELL];
#define g_acc g_zr
__device__ float4 g_cells[2 * NCELL * CAP];  // (x,y,z,idx-as-int)

// acc layout:
//  [0:14)   s0 grouped moments; [16:30) s1 grouped moments
//  [32:64)  s0 z stats (sum16 @32, sq16 @48)
//  [64:128) s1 z stats (sum32 @64, sq32 @96)
//  [160:288) final sum128 ; [288:416) final sq128

// ---------------- scatter points into 1.6m xy-cells --------------------------
__global__ void k_scatter(const float* __restrict__ pxyz) {
    int* ccnt = (int*)(g_zr + 512);
    int gid = blockIdx.x * 256 + threadIdx.x;     // 32768
    int b = gid >> 14;
    const float* p = pxyz + (size_t)gid * 3;
    float x = p[0], y = p[1], z = p[2];
    int cx = min(max((int)floorf((x + 70.4f) * 0.625f), 0), NXC - 1);
    int cy = min(max((int)floorf((y + 40.0f) * 0.625f), 0), NYC - 1);
    int cell = b * NCELL + cy * NXC + cx;
    int slot = atomicAdd(&ccnt[cell], 1);
    if (slot < CAP)
        g_cells[(size_t)cell * CAP + slot] =
            make_float4(x, y, z, __int_as_float(gid & 16383));
}

// ---------------- ball query + moments, with BEV gather co-resident ----------
// grid = 512 (group warps) + 4096 (bev rows)
__global__ void __launch_bounds__(256) k_group2(
        const float* __restrict__ kp, const float* __restrict__ pxyz,
        const float* __restrict__ pfeat, const float* __restrict__ sf,
        const int* __restrict__ pstride) {
    if (blockIdx.x >= 512) {               // ---- BEV bilinear gather part ----
        int row = blockIdx.x - 512;        // 0..4095
        int b = row >> 11;
        float stride = (float)pstride[0];
        float kx = kp[row * 3 + 0];
        float ky = kp[row * 3 + 1];
        float x = (kx - (-70.4f)) / 0.1f / stride;
        float y = (ky - (-40.0f)) / 0.1f / stride;
        int xi = (int)floorf(x), yi = (int)floorf(y);
        int x0 = min(max(xi, 0), WBEV - 1), x1 = min(max(xi + 1, 0), WBEV - 1);
        int y0 = min(max(yi, 0), HBEV - 1), y1 = min(max(yi + 1, 0), HBEV - 1);
        float x0f = (float)x0, x1f = (float)x1, y0f = (float)y0, y1f = (float)y1;
        float wa = (x1f - x) * (y1f - y);
        float wb = (x1f - x) * (y - y0f);
        float wc = (x - x0f) * (y1f - y);
        float wd = (x - x0f) * (y - y0f);
        const float* base = sf + (size_t)b * CBEV * HBEV * WBEV;
        int c = threadIdx.x;               // 256 threads = channels
        const float* pc = base + (size_t)c * (HBEV * WBEV);
        float Ia = __ldg(pc + y0 * WBEV + x0);
        float Ib = __ldg(pc + y1 * WBEV + x0);
        float Ic = __ldg(pc + y0 * WBEV + x1);
        float Id = __ldg(pc + y1 * WBEV + x1);
        g_feats[row * FEAT_DIM + c] = Ia * wa + Ib * wb + Ic * wc + Id * wd;
        return;
    }
    // ---- ball query part ----
    __shared__ int s_hits[8][32];
    __shared__ int s_cnt[8];
    __shared__ float smA[28];          // [0:14) scale0 moments, [14:28) scale1
    const int* ccnt = (const int*)(g_zr + 512);
    int tid = threadIdx.x;
    int wib = tid >> 5, lane = tid & 31;
    if (tid < 28) smA[tid] = 0.f;
    int kpid = blockIdx.x * 8 + wib;              // 512 CTAs x 8 warps = 4096
    int b = kpid >> 11;
    float kx = kp[kpid * 3 + 0], ky = kp[kpid * 3 + 1], kz = kp[kpid * 3 + 2];
    if (lane == 0) s_cnt[wib] = 0;
    __syncthreads();
    const float R0SQ = (float)(0.4 * 0.4);
    const float R1SQ = (float)(0.8 * 0.8);
    int cx0 = min(max((int)floorf((kx - 0.81f + 70.4f) * 0.625f), 0), NXC - 1);
    int cx1 = min(max((int)floorf((kx + 0.81f + 70.4f) * 0.625f), 0), NXC - 1);
    int cy0 = min(max((int)floorf((ky - 0.81f + 40.0f) * 0.625f), 0), NYC - 1);
    int cy1 = min(max((int)floorf((ky + 0.81f + 40.0f) * 0.625f), 0), NYC - 1);
    for (int cy = cy0; cy <= cy1; cy++) {
        for (int cx = cx0; cx <= cx1; cx++) {
            int cell = b * NCELL + cy * NXC + cx;
            int cnt = min(ccnt[cell], CAP);
            const float4* bp = &g_cells[(size_t)cell * CAP];
            for (int i = lane; i < cnt; i += 32) {
                float4 p = bp[i];
                float dx = kx - p.x, dy = ky - p.y, dz = kz - p.z;
                float d = __fadd_rn(__fadd_rn(__fmul_rn(dx, dx), __fmul_rn(dy, dy)),
                                    __fmul_rn(dz, dz));
                if (d < R1SQ) {
                    int pos = atomicAdd(&s_cnt[wib], 1);
                    if (pos < 32)
                        s_hits[wib][pos] = (__float_as_int(p.w) << 1) | (d < R0SQ ? 1 : 0);
                }
            }
        }
    }
    __syncwarp();
    int cnt = min(s_cnt[wib], 32);
    if (lane == 0 && cnt > 1) {            // insertion sort by (idx<<1|r0) = idx order
        for (int i = 1; i < cnt; i++) {
            int key = s_hits[wib][i];
            int j = i - 1;
            while (j >= 0 && s_hits[wib][j] > key) { s_hits[wib][j + 1] = s_hits[wib][j]; j--; }
            s_hits[wib][j + 1] = key;
        }
    }
    __syncwarp();
    int ent = (lane < cnt) ? s_hits[wib][lane] : 0;
    unsigned mask0 = __ballot_sync(FULLMASK, (lane < cnt) && (ent & 1));
    int n0 = __popc(mask0);
    int scale = (lane < 16) ? 1 : 0;       // lanes 0-15: scale1; 16-31: scale0
    int s = scale ? lane : (lane - 16);
    int myidx = -1;
    if (scale) {
        if (cnt > 0) myidx = ((s < cnt) ? s_hits[wib][s] : s_hits[wib][0]) >> 1;
    } else {
        if (n0 > 0) {
            int target = (s < n0) ? s : 0;
            unsigned m = mask0;
            for (int t = 0; t < target; t++) m &= m - 1;
            int pos = __ffs(m) - 1;
            myidx = s_hits[wib][pos] >> 1;
        }
    }
    float4 out = make_float4(0.f, 0.f, 0.f, 0.f);
    if (myidx >= 0) {
        const float* pp = pxyz + ((size_t)b * NN + myidx) * 3;
        out.x = pp[0] - kx;
        out.y = pp[1] - ky;
        out.z = pp[2] - kz;
        out.w = pfeat[(size_t)b * NN + myidx];
    }
    if (scale) g_g1[(size_t)kpid * 16 + s] = out;
    else       g_g0[(size_t)kpid * 16 + s] = out;
    if (s == 0) {
        if (scale) g_e1[kpid] = (cnt == 0);
        else       g_e0[kpid] = (n0 == 0);
    }
    // fused moments: width-16 shuffle reduce, per-half-warp
    float mm[14];
    mm[0] = out.x; mm[1] = out.y; mm[2] = out.z; mm[3] = out.w;
    mm[4] = out.x * out.x; mm[5] = out.x * out.y; mm[6] = out.x * out.z; mm[7] = out.x * out.w;
    mm[8] = out.y * out.y; mm[9] = out.y * out.z; mm[10] = out.y * out.w;
    mm[11] = out.z * out.z; mm[12] = out.z * out.w; mm[13] = out.w * out.w;
#pragma unroll
    for (int v = 0; v < 14; v++) {
        float val = mm[v];
        val += __shfl_down_sync(FULLMASK, val, 8, 16);
        val += __shfl_down_sync(FULLMASK, val, 4, 16);
        val += __shfl_down_sync(FULLMASK, val, 2, 16);
        val += __shfl_down_sync(FULLMASK, val, 1, 16);
        mm[v] = val;
    }
    if (lane == 16) {          // scale0 totals
#pragma unroll
        for (int v = 0; v < 14; v++) atomicAdd(&smA[v], mm[v]);
    } else if (lane == 0) {    // scale1 totals
#pragma unroll
        for (int v = 0; v < 14; v++) atomicAdd(&smA[14 + v], mm[v]);
    }
    __syncthreads();
    if (tid < 28) atomicAdd(&g_acc[(tid < 14) ? tid : (tid + 2)], smA[tid]);
}

// ---------------- fused MLP + in-register z stats, both scales ---------------
__global__ void __launch_bounds__(256) k_mlp2(
        const float* __restrict__ W0a, const float* __restrict__ gamma0a,
        const float* __restrict__ beta0a, const float* __restrict__ W1a,
        const float* __restrict__ W0b, const float* __restrict__ gamma0b,
        const float* __restrict__ beta0b, const float* __restrict__ W1b) {
    __shared__ float sW0[64];
    __shared__ float sW1[512];
    __shared__ float sA[16], sB[16];
    __shared__ float s_red[64];
    int tid = threadIdx.x;
    int lane = tid & 31;
    int bid = blockIdx.x;                     // 512 blocks: <256 scale0, else scale1
    bool s1 = bid >= 256;
    const float* W0 = s1 ? W0b : W0a;
    const float* W1 = s1 ? W1b : W1a;
    const float* gamma0 = s1 ? gamma0b : gamma0a;
    const float* beta0 = s1 ? beta0b : beta0a;
    int C = s1 ? 32 : 16;
    int momOff = s1 ? 16 : 0;
    if (tid < 64) { sW0[tid] = W0[tid]; s_red[tid] = 0.f; }
    for (int i = tid; i < C * 16; i += 256) sW1[i] = W1[i];
    __syncthreads();
    if (tid < 16) {
        float w0 = sW0[tid * 4 + 0], w1 = sW0[tid * 4 + 1];
        float w2 = sW0[tid * 4 + 2], w3 = sW0[tid * 4 + 3];
        const float* m = &g_acc[momOff];
        float mean = (w0 * m[0] + w1 * m[1] + w2 * m[2] + w3 * m[3]) * (1.0f / 65536.0f);
        float e2 = w0 * w0 * m[4] + w1 * w1 * m[8] + w2 * w2 * m[11] + w3 * w3 * m[13]
                 + 2.f * (w0 * w1 * m[5] + w0 * w2 * m[6] + w0 * w3 * m[7]
                        + w1 * w2 * m[9] + w1 * w3 * m[10] + w2 * w3 * m[12]);
        e2 *= (1.0f / 65536.0f);
        float var = e2 - mean * mean;
        float sc = gamma0[tid] * rsqrtf(var + 1e-5f);
        sA[tid] = sc;
        sB[tid] = beta0[tid] - mean * sc;
    }
    __syncthreads();
    int row = (bid & 255) * 256 + tid;
    float4 g = (s1 ? g_g1 : g_g0)[row];
    float y[16];
#pragma unroll
    for (int o = 0; o < 16; o++) {
        float z = g.x * sW0[o * 4 + 0] + g.y * sW0[o * 4 + 1] +
                  g.z * sW0[o * 4 + 2] + g.w * sW0[o * 4 + 3];
        y[o] = fmaxf(z * sA[o] + sB[o], 0.f);
    }
    if (!s1) {
        float zreg[16];
#pragma unroll
        for (int o = 0; o < 16; o++) {
            float z = 0.f;
#pragma unroll
            for (int c = 0; c < 16; c++) z += y[c] * sW1[o * 16 + c];
            zreg[o] = z;
        }
#pragma unroll
        for (int o4 = 0; o4 < 4; o4++)
            g_z0[(size_t)row * 4 + o4] = make_float4(zreg[o4 * 4 + 0], zreg[o4 * 4 + 1],
                                                     zreg[o4 * 4 + 2], zreg[o4 * 4 + 3]);
        // per-warp stat reduction: 16 sums + 16 squares
#pragma unroll
        for (int o = 0; o < 16; o++) {
            float sv = zreg[o];
            float qv = zreg[o] * zreg[o];
            sv += __shfl_down_sync(FULLMASK, sv, 16); qv += __shfl_down_sync(FULLMASK, qv, 16);
            sv += __shfl_down_sync(FULLMASK, sv, 8);  qv += __shfl_down_sync(FULLMASK, qv, 8);
            sv += __shfl_down_sync(FULLMASK, sv, 4);  qv += __shfl_down_sync(FULLMASK, qv, 4);
            sv += __shfl_down_sync(FULLMASK, sv, 2);  qv += __shfl_down_sync(FULLMASK, qv, 2);
            sv += __shfl_down_sync(FULLMASK, sv, 1);  qv += __shfl_down_sync(FULLMASK, qv, 1);
            if (lane == 0) {
                atomicAdd(&s_red[o], sv);
                atomicAdd(&s_red[16 + o], qv);
            }
        }
        __syncthreads();
        if (tid < 32) atomicAdd(&g_acc[32 + tid], s_red[tid]);
    } else {
        float zreg[32];
#pragma unroll
        for (int o = 0; o < 32; o++) {
            float z = 0.f;
#pragma unroll
            for (int c = 0; c < 16; c++) z += y[c] * sW1[o * 16 + c];
            zreg[o] = z;
        }
#pragma unroll
        for (int o4 = 0; o4 < 8; o4++)
            g_z1[(size_t)row * 8 + o4] = make_float4(zreg[o4 * 4 + 0], zreg[o4 * 4 + 1],
                                                     zreg[o4 * 4 + 2], zreg[o4 * 4 + 3]);
#pragma unroll
        for (int o = 0; o < 32; o++) {
            float sv = zreg[o];
            float qv = zreg[o] * zreg[o];
            sv += __shfl_down_sync(FULLMASK, sv, 16); qv += __shfl_down_sync(FULLMASK, qv, 16);
            sv += __shfl_down_sync(FULLMASK, sv, 8);  qv += __shfl_down_sync(FULLMASK, qv, 8);
            sv += __shfl_down_sync(FULLMASK, sv, 4);  qv += __shfl_down_sync(FULLMASK, qv, 4);
            sv += __shfl_down_sync(FULLMASK, sv, 2);  qv += __shfl_down_sync(FULLMASK, qv, 2);
            sv += __shfl_down_sync(FULLMASK, sv, 1);  qv += __shfl_down_sync(FULLMASK, qv, 1);
            if (lane == 0) {
                atomicAdd(&s_red[o & 31], sv);          // sums in s_red[0:32)
                atomicAdd(&s_red[32 + (o & 31)], qv);   // squares in s_red[32:64)
            }
        }
        __syncthreads();
        if (tid < 64) atomicAdd(&g_acc[64 + tid], s_red[tid]);
    }
}

// ---------------- bn+relu+maxpool, 4 channels per thread (float4) -----------
template <int C>
__device__ __forceinline__ void pool_body4(
        int gid, const float* __restrict__ gamma, const float* __restrict__ beta,
        const float4* __restrict__ Z4, const unsigned char* __restrict__ E,
        int accOff, int colbase) {
    const int G = C / 4;
    int k = gid / G, g4 = gid - k * G;
    int o = g4 * 4;
    float a0, a1, a2, a3, b0, b1, b2, b3;
    {
        float mean = g_acc[accOff + o + 0] * (1.0f / 65536.0f);
        float var = g_acc[accOff + C + o + 0] * (1.0f / 65536.0f) - mean * mean;
        a0 = gamma[o + 0] * rsqrtf(var + 1e-5f); b0 = beta[o + 0] - mean * a0;
    }
    {
        float mean = g_acc[accOff + o + 1] * (1.0f / 65536.0f);
        float var = g_acc[accOff + C + o + 1] * (1.0f / 65536.0f) - mean * mean;
        a1 = gamma[o + 1] * rsqrtf(var + 1e-5f); b1 = beta[o + 1] - mean * a1;
    }
    {
        float mean = g_acc[accOff + o + 2] * (1.0f / 65536.0f);
        float var = g_acc[accOff + C + o + 2] * (1.0f / 65536.0f) - mean * mean;
        a2 = gamma[o + 2] * rsqrtf(var + 1e-5f); b2 = beta[o + 2] - mean * a2;
    }
    {
        float mean = g_acc[accOff + o + 3] * (1.0f / 65536.0f);
        float var = g_acc[accOff + C + o + 3] * (1.0f / 65536.0f) - mean * mean;
        a3 = gamma[o + 3] * rsqrtf(var + 1e-5f); b3 = beta[o + 3] - mean * a3;
    }
    const float4* zp = Z4 + (size_t)k * 16 * G + g4;
    float m0 = 0.f, m1 = 0.f, m2 = 0.f, m3 = 0.f;
#pragma unroll
    for (int s = 0; s < 16; s++) {
        float4 v = zp[s * G];
        m0 = fmaxf(m0, fmaxf(v.x * a0 + b0, 0.f));
        m1 = fmaxf(m1, fmaxf(v.y * a1 + b1, 0.f));
        m2 = fmaxf(m2, fmaxf(v.z * a2 + b2, 0.f));
        m3 = fmaxf(m3, fmaxf(v.w * a3 + b3, 0.f));
    }
    if (E[k]) { m0 = 0.f; m1 = 0.f; m2 = 0.f; m3 = 0.f; }
    *(float4*)(g_feats + (size_t)k * FEAT_DIM + colbase + o) =
        make_float4(m0, m1, m2, m3);
}

__global__ void __launch_bounds__(256) k_poolB(
        const float* __restrict__ g1a, const float* __restrict__ b1a,
        const float* __restrict__ g1b, const float* __restrict__ b1b) {
    int bid = blockIdx.x;                  // 192 blocks: <64 scale0, else scale1
    if (bid < 64)
        pool_body4<16>(bid * 256 + threadIdx.x, g1a, b1a, g_z0, g_e0, 32, 256);
    else
        pool_body4<32>((bid - 64) * 256 + threadIdx.x, g1b, b1b, g_z1, g_e1, 64, 272);
}

// ---------------- final GEMM: feats(4096,304) @ Wf(128,304)^T + stats -------
__global__ void __launch_bounds__(256) k_fgemm(const float* __restrict__ Wf) {
    __shared__ float sF[32 * FEAT_DIM];          // 38.9 KB
    __shared__ float sS[128], sQ[128];
    int tid = threadIdx.x;
    int r0 = blockIdx.x * 32;                    // 128 CTAs
    const float4* src = (const float4*)(g_feats + (size_t)r0 * FEAT_DIM);
    float4* dst = (float4*)sF;
    for (int i = tid; i < 32 * (FEAT_DIM / 4); i += 256) dst[i] = src[i];
    if (tid < 128) { sS[tid] = 0.f; sQ[tid] = 0.f; }
    __syncthreads();
    int o = tid & 127;
    int rh = tid >> 7;
    float acc_[16];
#pragma unroll
    for (int r = 0; r < 16; r++) acc_[r] = 0.f;
    const float4* wrow = (const float4*)(Wf + (size_t)o * FEAT_DIM);
    const float4* fbase = (const float4*)sF + (size_t)(rh * 16) * (FEAT_DIM / 4);
#pragma unroll 2
    for (int c4 = 0; c4 < FEAT_DIM / 4; c4++) {
        float4 w = __ldg(wrow + c4);
#pragma unroll
        for (int r = 0; r < 16; r++) {
            float4 f = fbase[(size_t)r * (FEAT_DIM / 4) + c4];
            acc_[r] += w.x * f.x + w.y * f.y + w.z * f.z + w.w * f.w;
        }
    }
    float S = 0.f, Q = 0.f;
#pragma unroll
    for (int r = 0; r < 16; r++) {
        float z = acc_[r];
        g_fz[(size_t)(r0 + rh * 16 + r) * OUTC + o] = z;
        S += z; Q += z * z;
    }
    atomicAdd(&sS[o], S);
    atomicAdd(&sQ[o], Q);
    __syncthreads();
    if (tid < 128) {
        atomicAdd(&g_acc[160 + tid], sS[tid]);
        atomicAdd(&g_acc[288 + tid], sQ[tid]);
    }
}

// ---------------- final bn + relu -> d_out (float4) -------------------------
__global__ void k_fbn(const float* __restrict__ gamma, const float* __restrict__ beta,
                      float* __restrict__ out) {
    int gid = blockIdx.x * 256 + threadIdx.x;     // 131072 float4s
    int o4 = (gid & 31) * 4;                      // channel base
    float4 z = ((const float4*)g_fz)[gid];
    float4 r;
    {
        float mean = g_acc[160 + o4 + 0] * (1.0f / 4096.0f);
        float var = g_acc[288 + o4 + 0] * (1.0f / 4096.0f) - mean * mean;
        r.x = fmaxf((z.x - mean) * rsqrtf(var + 1e-5f) * gamma[o4 + 0] + beta[o4 + 0], 0.f);
    }
    {
        float mean = g_acc[160 + o4 + 1] * (1.0f / 4096.0f);
        float var = g_acc[288 + o4 + 1] * (1.0f / 4096.0f) - mean * mean;
        r.y = fmaxf((z.y - mean) * rsqrtf(var + 1e-5f) * gamma[o4 + 1] + beta[o4 + 1], 0.f);
    }
    {
        float mean = g_acc[160 + o4 + 2] * (1.0f / 4096.0f);
        float var = g_acc[288 + o4 + 2] * (1.0f / 4096.0f) - mean * mean;
        r.z = fmaxf((z.z - mean) * rsqrtf(var + 1e-5f) * gamma[o4 + 2] + beta[o4 + 2], 0.f);
    }
    {
        float mean = g_acc[160 + o4 + 3] * (1.0f / 4096.0f);
        float var = g_acc[288 + o4 + 3] * (1.0f / 4096.0f) - mean * mean;
        r.w = fmaxf((z.w - mean) * rsqrtf(var + 1e-5f) * gamma[o4 + 3] + beta[o4 + 3], 0.f);
    }
    ((float4*)out)[gid] = r;
}

// ---------------- launch -----------------------------------------------------
extern "C" void kernel_launch(void* const* d_in, const int* in_sizes, int n_in,
                              void* d_out, int out_size) {
    const float* kp     = (const float*)d_in[0];
    const float* pxyz   = (const float*)d_in[1];
    const float* pfeat  = (const float*)d_in[2];
    const float* sf     = (const float*)d_in[3];
    const int*   stridep= (const int*)d_in[4];
    const float* W0_s0  = (const float*)d_in[5];
    const float* g0_s0  = (const float*)d_in[6];
    const float* b0_s0  = (const float*)d_in[7];
    const float* W1_s0  = (const float*)d_in[8];
    const float* g1_s0  = (const float*)d_in[9];
    const float* b1_s0  = (const float*)d_in[10];
    const float* W0_s1  = (const float*)d_in[11];
    const float* g0_s1  = (const float*)d_in[12];
    const float* b0_s1  = (const float*)d_in[13];
    const float* W1_s1  = (const float*)d_in[14];
    const float* g1_s1  = (const float*)d_in[15];
    const float* b1_s1  = (const float*)d_in[16];
    const float* Wf     = (const float*)d_in[17];
    const float* gf     = (const float*)d_in[18];
    const float* bf     = (const float*)d_in[19];
    (void)in_sizes; (void)n_in; (void)out_size;

    void* zrp; cudaGetSymbolAddress(&zrp, g_zr);
    cudaMemsetAsync(zrp, 0, (512 + 2 * NCELL) * sizeof(float));

    k_scatter<<<128, 256>>>(pxyz);
    k_group2<<<4608, 256>>>(kp, pxyz, pfeat, sf, stridep);

    k_mlp2<<<512, 256>>>(W0_s0, g0_s0, b0_s0, W1_s0, W0_s1, g0_s1, b0_s1, W1_s1);
    k_poolB<<<192, 256>>>(g1_s0, b1_s0, g1_s1, b1_s1);

    k_fgemm<<<128, 256>>>(Wf);
    k_fbn<<<512, 256>>>(gf, bf, (float*)d_out);
}

// round 15
// speedup vs baseline: 1.2479x; 1.2479x over previous
#include <cuda_runtime.h>
#include <math.h>

#define FULLMASK 0xffffffffu

#define BB 2
#define KK 2048
#define NN 16384
#define SROWS 65536      // B*K*16 sample-rows
#define ROWS 4096        // B*K
#define CBEV 256
#define HBEV 100
#define WBEV 176
#define FEAT_DIM 304
#define OUTC 128

// spatial hash for ball query
#define NXC 89
#define NYC 51
#define NCELL (NXC * NYC)    // 4539 per batch
#define CAP 64

// ---------------- scratch (device globals; no allocs allowed) ----------------
__device__ float4 g_g0[SROWS];            // grouped scale0: (rel xyz, feat)
__device__ float4 g_g1[SROWS];            // grouped scale1
__device__ unsigned char g_e0[ROWS];
__device__ unsigned char g_e1[ROWS];
__device__ float2 g_mm0[ROWS * 16];       // per-(kp,ch) (max,min) of z, scale0
__device__ float2 g_mm1[ROWS * 32];       // scale1
__device__ float g_feats[ROWS * FEAT_DIM];
__device__ float g_fz[ROWS * OUTC];
// one zeroed region: [0:512) acc floats; [512:512+2*NCELL) ccnt ints
__device__ float g_zr[512 + 2 * NCELL];
#define g_acc g_zr
__device__ float4 g_cells[2 * NCELL * CAP];  // (x,y,z,idx-as-int)

// acc layout:
//  [0:14)   s0 grouped moments; [16:30) s1 grouped moments
//  [32:64)  s0 z stats (sum16 @32, sq16 @48)
//  [64:128) s1 z stats (sum32 @64, sq32 @96)
//  [160:288) final sum128 ; [288:416) final sq128

// ---------------- scatter points into 1.6m xy-cells --------------------------
__global__ void k_scatter(const float* __restrict__ pxyz) {
    int* ccnt = (int*)(g_zr + 512);
    int gid = blockIdx.x * 256 + threadIdx.x;     // 32768
    int b = gid >> 14;
    const float* p = pxyz + (size_t)gid * 3;
    float x = p[0], y = p[1], z = p[2];
    int cx = min(max((int)floorf((x + 70.4f) * 0.625f), 0), NXC - 1);
    int cy = min(max((int)floorf((y + 40.0f) * 0.625f), 0), NYC - 1);
    int cell = b * NCELL + cy * NXC + cx;
    int slot = atomicAdd(&ccnt[cell], 1);
    if (slot < CAP)
        g_cells[(size_t)cell * CAP + slot] =
            make_float4(x, y, z, __int_as_float(gid & 16383));
}

// ---------------- ball query + moments, with BEV gather co-resident ----------
// grid = 512 (group warps) + 4096 (bev rows)
__global__ void __launch_bounds__(256) k_group2(
        const float* __restrict__ kp, const float* __restrict__ pxyz,
        const float* __restrict__ pfeat, const float* __restrict__ sf,
        const int* __restrict__ pstride) {
    if (blockIdx.x >= 512) {               // ---- BEV bilinear gather part ----
        int row = blockIdx.x - 512;        // 0..4095
        int b = row >> 11;
        float stride = (float)pstride[0];
        float kx = kp[row * 3 + 0];
        float ky = kp[row * 3 + 1];
        float x = (kx - (-70.4f)) / 0.1f / stride;
        float y = (ky - (-40.0f)) / 0.1f / stride;
        int xi = (int)floorf(x), yi = (int)floorf(y);
        int x0 = min(max(xi, 0), WBEV - 1), x1 = min(max(xi + 1, 0), WBEV - 1);
        int y0 = min(max(yi, 0), HBEV - 1), y1 = min(max(yi + 1, 0), HBEV - 1);
        float x0f = (float)x0, x1f = (float)x1, y0f = (float)y0, y1f = (float)y1;
        float wa = (x1f - x) * (y1f - y);
        float wb = (x1f - x) * (y - y0f);
        float wc = (x - x0f) * (y1f - y);
        float wd = (x - x0f) * (y - y0f);
        const float* base = sf + (size_t)b * CBEV * HBEV * WBEV;
        int c = threadIdx.x;               // 256 threads = channels
        const float* pc = base + (size_t)c * (HBEV * WBEV);
        float Ia = __ldg(pc + y0 * WBEV + x0);
        float Ib = __ldg(pc + y1 * WBEV + x0);
        float Ic = __ldg(pc + y0 * WBEV + x1);
        float Id = __ldg(pc + y1 * WBEV + x1);
        g_feats[row * FEAT_DIM + c] = Ia * wa + Ib * wb + Ic * wc + Id * wd;
        return;
    }
    // ---- ball query part ----
    __shared__ int s_hits[8][32];
    __shared__ int s_cnt[8];
    __shared__ float smA[28];          // [0:14) scale0 moments, [14:28) scale1
    const int* ccnt = (const int*)(g_zr + 512);
    int tid = threadIdx.x;
    int wib = tid >> 5, lane = tid & 31;
    if (tid < 28) smA[tid] = 0.f;
    int kpid = blockIdx.x * 8 + wib;              // 512 CTAs x 8 warps = 4096
    int b = kpid >> 11;
    float kx = kp[kpid * 3 + 0], ky = kp[kpid * 3 + 1], kz = kp[kpid * 3 + 2];
    if (lane == 0) s_cnt[wib] = 0;
    __syncthreads();
    const float R0SQ = (float)(0.4 * 0.4);
    const float R1SQ = (float)(0.8 * 0.8);
    int cx0 = min(max((int)floorf((kx - 0.81f + 70.4f) * 0.625f), 0), NXC - 1);
    int cx1 = min(max((int)floorf((kx + 0.81f + 70.4f) * 0.625f), 0), NXC - 1);
    int cy0 = min(max((int)floorf((ky - 0.81f + 40.0f) * 0.625f), 0), NYC - 1);
    int cy1 = min(max((int)floorf((ky + 0.81f + 40.0f) * 0.625f), 0), NYC - 1);
    for (int cy = cy0; cy <= cy1; cy++) {
        for (int cx = cx0; cx <= cx1; cx++) {
            int cell = b * NCELL + cy * NXC + cx;
            int cnt = min(ccnt[cell], CAP);
            const float4* bp = &g_cells[(size_t)cell * CAP];
            for (int i = lane; i < cnt; i += 32) {
                float4 p = bp[i];
                float dx = kx - p.x, dy = ky - p.y, dz = kz - p.z;
                float d = __fadd_rn(__fadd_rn(__fmul_rn(dx, dx), __fmul_rn(dy, dy)),
                                    __fmul_rn(dz, dz));
                if (d < R1SQ) {
                    int pos = atomicAdd(&s_cnt[wib], 1);
                    if (pos < 32)
                        s_hits[wib][pos] = (__float_as_int(p.w) << 1) | (d < R0SQ ? 1 : 0);
                }
            }
        }
    }
    __syncwarp();
    int cnt = min(s_cnt[wib], 32);
    if (lane == 0 && cnt > 1) {            // insertion sort by (idx<<1|r0) = idx order
        for (int i = 1; i < cnt; i++) {
            int key = s_hits[wib][i];
            int j = i - 1;
            while (j >= 0 && s_hits[wib][j] > key) { s_hits[wib][j + 1] = s_hits[wib][j]; j--; }
            s_hits[wib][j + 1] = key;
        }
    }
    __syncwarp();
    int ent = (lane < cnt) ? s_hits[wib][lane] : 0;
    unsigned mask0 = __ballot_sync(FULLMASK, (lane < cnt) && (ent & 1));
    int n0 = __popc(mask0);
    int scale = (lane < 16) ? 1 : 0;       // lanes 0-15: scale1; 16-31: scale0
    int s = scale ? lane : (lane - 16);
    int myidx = -1;
    if (scale) {
        if (cnt > 0) myidx = ((s < cnt) ? s_hits[wib][s] : s_hits[wib][0]) >> 1;
    } else {
        if (n0 > 0) {
            int target = (s < n0) ? s : 0;
            unsigned m = mask0;
            for (int t = 0; t < target; t++) m &= m - 1;
            int pos = __ffs(m) - 1;
            myidx = s_hits[wib][pos] >> 1;
        }
    }
    float4 out = make_float4(0.f, 0.f, 0.f, 0.f);
    if (myidx >= 0) {
        const float* pp = pxyz + ((size_t)b * NN + myidx) * 3;
        out.x = pp[0] - kx;
        out.y = pp[1] - ky;
        out.z = pp[2] - kz;
        out.w = pfeat[(size_t)b * NN + myidx];
    }
    if (scale) g_g1[(size_t)kpid * 16 + s] = out;
    else       g_g0[(size_t)kpid * 16 + s] = out;
    if (s == 0) {
        if (scale) g_e1[kpid] = (cnt == 0);
        else       g_e0[kpid] = (n0 == 0);
    }
    // fused moments: width-16 shuffle reduce, per-half-warp
    float mm[14];
    mm[0] = out.x; mm[1] = out.y; mm[2] = out.z; mm[3] = out.w;
    mm[4] = out.x * out.x; mm[5] = out.x * out.y; mm[6] = out.x * out.z; mm[7] = out.x * out.w;
    mm[8] = out.y * out.y; mm[9] = out.y * out.z; mm[10] = out.y * out.w;
    mm[11] = out.z * out.z; mm[12] = out.z * out.w; mm[13] = out.w * out.w;
#pragma unroll
    for (int v = 0; v < 14; v++) {
        float val = mm[v];
        val += __shfl_down_sync(FULLMASK, val, 8, 16);
        val += __shfl_down_sync(FULLMASK, val, 4, 16);
        val += __shfl_down_sync(FULLMASK, val, 2, 16);
        val += __shfl_down_sync(FULLMASK, val, 1, 16);
        mm[v] = val;
    }
    if (lane == 16) {          // scale0 totals
#pragma unroll
        for (int v = 0; v < 14; v++) atomicAdd(&smA[v], mm[v]);
    } else if (lane == 0) {    // scale1 totals
#pragma unroll
        for (int v = 0; v < 14; v++) atomicAdd(&smA[14 + v], mm[v]);
    }
    __syncthreads();
    if (tid < 28) atomicAdd(&g_acc[(tid < 14) ? tid : (tid + 2)], smA[tid]);
}

// ---------------- fused MLP + CTA-local z reduce (no z materialization) ------
__global__ void __launch_bounds__(256) k_mlp2(
        const float* __restrict__ W0a, const float* __restrict__ gamma0a,
        const float* __restrict__ beta0a, const float* __restrict__ W1a,
        const float* __restrict__ W0b, const float* __restrict__ gamma0b,
        const float* __restrict__ beta0b, const float* __restrict__ W1b) {
    __shared__ float sW0[64];
    __shared__ float sW1[512];
    __shared__ float sA[16], sB[16];
    __shared__ float s_red[64];
    __shared__ float sZ[256 * 33];            // 256 rows x up to 32 ch, pad 33
    int tid = threadIdx.x;
    int bid = blockIdx.x;                     // 512 blocks: <256 scale0, else scale1
    bool s1 = bid >= 256;
    const float* W0 = s1 ? W0b : W0a;
    const float* W1 = s1 ? W1b : W1a;
    const float* gamma0 = s1 ? gamma0b : gamma0a;
    const float* beta0 = s1 ? beta0b : beta0a;
    int C = s1 ? 32 : 16;
    int momOff = s1 ? 16 : 0;
    if (tid < 64) { sW0[tid] = W0[tid]; s_red[tid] = 0.f; }
    for (int i = tid; i < C * 16; i += 256) sW1[i] = W1[i];
    __syncthreads();
    if (tid < 16) {
        float w0 = sW0[tid * 4 + 0], w1 = sW0[tid * 4 + 1];
        float w2 = sW0[tid * 4 + 2], w3 = sW0[tid * 4 + 3];
        const float* m = &g_acc[momOff];
        float mean = (w0 * m[0] + w1 * m[1] + w2 * m[2] + w3 * m[3]) * (1.0f / 65536.0f);
        float e2 = w0 * w0 * m[4] + w1 * w1 * m[8] + w2 * w2 * m[11] + w3 * w3 * m[13]
                 + 2.f * (w0 * w1 * m[5] + w0 * w2 * m[6] + w0 * w3 * m[7]
                        + w1 * w2 * m[9] + w1 * w3 * m[10] + w2 * w3 * m[12]);
        e2 *= (1.0f / 65536.0f);
        float var = e2 - mean * mean;
        float sc = gamma0[tid] * rsqrtf(var + 1e-5f);
        sA[tid] = sc;
        sB[tid] = beta0[tid] - mean * sc;
    }
    __syncthreads();
    int row = (bid & 255) * 256 + tid;
    float4 g = (s1 ? g_g1 : g_g0)[row];
    float y[16];
#pragma unroll
    for (int o = 0; o < 16; o++) {
        float z = g.x * sW0[o * 4 + 0] + g.y * sW0[o * 4 + 1] +
                  g.z * sW0[o * 4 + 2] + g.w * sW0[o * 4 + 3];
        y[o] = fmaxf(z * sA[o] + sB[o], 0.f);
    }
    int kpbase = (bid & 255) * 16;
    if (!s1) {
#pragma unroll
        for (int o = 0; o < 16; o++) {
            float z = 0.f;
#pragma unroll
            for (int c = 0; c < 16; c++) z += y[c] * sW1[o * 16 + c];
            sZ[tid * 33 + o] = z;
        }
        __syncthreads();
        // thread = (k, o): 16 kp x 16 ch = 256 items
        int k = tid >> 4, o = tid & 15;
        float mx = -3.4e38f, mn = 3.4e38f, sm = 0.f, sq = 0.f;
#pragma unroll
        for (int s = 0; s < 16; s++) {
            float v = sZ[(k * 16 + s) * 33 + o];
            mx = fmaxf(mx, v); mn = fminf(mn, v);
            sm += v; sq += v * v;
        }
        atomicAdd(&s_red[o], sm);
        atomicAdd(&s_red[16 + o], sq);
        g_mm0[(size_t)(kpbase + k) * 16 + o] = make_float2(mx, mn);
        __syncthreads();
        if (tid < 32) atomicAdd(&g_acc[32 + tid], s_red[tid]);
    } else {
#pragma unroll
        for (int o = 0; o < 32; o++) {
            float z = 0.f;
#pragma unroll
            for (int c = 0; c < 16; c++) z += y[c] * sW1[o * 16 + c];
            sZ[tid * 33 + o] = z;
        }
        __syncthreads();
        // 16 kp x 32 ch = 512 items, 2 per thread
#pragma unroll
        for (int half = 0; half < 2; half++) {
            int it = half * 256 + tid;
            int k = it >> 5, o = it & 31;
            float mx = -3.4e38f, mn = 3.4e38f, sm = 0.f, sq = 0.f;
#pragma unroll
            for (int s = 0; s < 16; s++) {
                float v = sZ[(k * 16 + s) * 33 + o];
                mx = fmaxf(mx, v); mn = fminf(mn, v);
                sm += v; sq += v * v;
            }
            atomicAdd(&s_red[o], sm);
            atomicAdd(&s_red[32 + o], sq);
            g_mm1[(size_t)(kpbase + k) * 32 + o] = make_float2(mx, mn);
        }
        __syncthreads();
        if (tid < 64) atomicAdd(&g_acc[64 + tid], s_red[tid]);
    }
}

// ---------------- pool from (max,min): bn1+relu+empty-gate -> feats ----------
__global__ void __launch_bounds__(256) k_poolmm(
        const float* __restrict__ g1a, const float* __restrict__ b1a,
        const float* __restrict__ g1b, const float* __restrict__ b1b) {
    int gid = blockIdx.x * 256 + threadIdx.x;     // 768 CTAs -> 196608
    int k, o, C, accOff, colbase;
    float2 mm;
    const float *gamma, *beta;
    const unsigned char* E;
    if (gid < 65536) {
        C = 16; k = gid >> 4; o = gid & 15; accOff = 32; colbase = 256;
        mm = g_mm0[gid]; gamma = g1a; beta = b1a; E = g_e0;
    } else {
        int g2 = gid - 65536;
        C = 32; k = g2 >> 5; o = g2 & 31; accOff = 64; colbase = 272;
        mm = g_mm1[g2]; gamma = g1b; beta = b1b; E = g_e1;
    }
    float mean = g_acc[accOff + o] * (1.0f / 65536.0f);
    float var = g_acc[accOff + C + o] * (1.0f / 65536.0f) - mean * mean;
    float a = gamma[o] * rsqrtf(var + 1e-5f);
    float bb = beta[o] - mean * a;
    float v = (a >= 0.f) ? mm.x : mm.y;       // monotone: max for a>=0, min for a<0
    float r = fmaxf(v * a + bb, 0.f);
    if (E[k]) r = 0.f;
    g_feats[(size_t)k * FEAT_DIM + colbase + o] = r;
}

// ---------------- final GEMM: feats(4096,304) @ Wf(128,304)^T + stats -------
__global__ void __launch_bounds__(256) k_fgemm(const float* __restrict__ Wf) {
    __shared__ float sF[32 * FEAT_DIM];          // 38.9 KB
    __shared__ float sS[128], sQ[128];
    int tid = threadIdx.x;
    int r0 = blockIdx.x * 32;                    // 128 CTAs
    const float4* src = (const float4*)(g_feats + (size_t)r0 * FEAT_DIM);
    float4* dst = (float4*)sF;
    for (int i = tid; i < 32 * (FEAT_DIM / 4); i += 256) dst[i] = src[i];
    if (tid < 128) { sS[tid] = 0.f; sQ[tid] = 0.f; }
    __syncthreads();
    int o = tid & 127;
    int rh = tid >> 7;
    float acc_[16];
#pragma unroll
    for (int r = 0; r < 16; r++) acc_[r] = 0.f;
    const float4* wrow = (const float4*)(Wf + (size_t)o * FEAT_DIM);
    const float4* fbase = (const float4*)sF + (size_t)(rh * 16) * (FEAT_DIM / 4);
#pragma unroll 2
    for (int c4 = 0; c4 < FEAT_DIM / 4; c4++) {
        float4 w = __ldg(wrow + c4);
#pragma unroll
        for (int r = 0; r < 16; r++) {
            float4 f = fbase[(size_t)r * (FEAT_DIM / 4) + c4];
            acc_[r] += w.x * f.x + w.y * f.y + w.z * f.z + w.w * f.w;
        }
    }
    float S = 0.f, Q = 0.f;
#pragma unroll
    for (int r = 0; r < 16; r++) {
        float z = acc_[r];
        g_fz[(size_t)(r0 + rh * 16 + r) * OUTC + o] = z;
        S += z; Q += z * z;
    }
    atomicAdd(&sS[o], S);
    atomicAdd(&sQ[o], Q);
    __syncthreads();
    if (tid < 128) {
        atomicAdd(&g_acc[160 + tid], sS[tid]);
        atomicAdd(&g_acc[288 + tid], sQ[tid]);
    }
}

// ---------------- final bn + relu -> d_out (float4) -------------------------
__global__ void k_fbn(const float* __restrict__ gamma, const float* __restrict__ beta,
                      float* __restrict__ out) {
    int gid = blockIdx.x * 256 + threadIdx.x;     // 131072 float4s
    int o4 = (gid & 31) * 4;                      // channel base
    float4 z = ((const float4*)g_fz)[gid];
    float4 r;
    {
        float mean = g_acc[160 + o4 + 0] * (1.0f / 4096.0f);
        float var = g_acc[288 + o4 + 0] * (1.0f / 4096.0f) - mean * mean;
        r.x = fmaxf((z.x - mean) * rsqrtf(var + 1e-5f) * gamma[o4 + 0] + beta[o4 + 0], 0.f);
    }
    {
        float mean = g_acc[160 + o4 + 1] * (1.0f / 4096.0f);
        float var = g_acc[288 + o4 + 1] * (1.0f / 4096.0f) - mean * mean;
        r.y = fmaxf((z.y - mean) * rsqrtf(var + 1e-5f) * gamma[o4 + 1] + beta[o4 + 1], 0.f);
    }
    {
        float mean = g_acc[160 + o4 + 2] * (1.0f / 4096.0f);
        float var = g_acc[288 + o4 + 2] * (1.0f / 4096.0f) - mean * mean;
        r.z = fmaxf((z.z - mean) * rsqrtf(var + 1e-5f) * gamma[o4 + 2] + beta[o4 + 2], 0.f);
    }
    {
        float mean = g_acc[160 + o4 + 3] * (1.0f / 4096.0f);
        float var = g_acc[288 + o4 + 3] * (1.0f / 4096.0f) - mean * mean;
        r.w = fmaxf((z.w - mean) * rsqrtf(var + 1e-5f) * gamma[o4 + 3] + beta[o4 + 3], 0.f);
    }
    ((float4*)out)[gid] = r;
}

// ---------------- launch -----------------------------------------------------
extern "C" void kernel_launch(void* const* d_in, const int* in_sizes, int n_in,
                              void* d_out, int out_size) {
    const float* kp     = (const float*)d_in[0];
    const float* pxyz   = (const float*)d_in[1];
    const float* pfeat  = (const float*)d_in[2];
    const float* sf     = (const float*)d_in[3];
    const int*   stridep= (const int*)d_in[4];
    const float* W0_s0  = (const float*)d_in[5];
    const float* g0_s0  = (const float*)d_in[6];
    const float* b0_s0  = (const float*)d_in[7];
    const float* W1_s0  = (const float*)d_in[8];
    const float* g1_s0  = (const float*)d_in[9];
    const float* b1_s0  = (const float*)d_in[10];
    const float* W0_s1  = (const float*)d_in[11];
    const float* g0_s1  = (const float*)d_in[12];
    const float* b0_s1  = (const float*)d_in[13];
    const float* W1_s1  = (const float*)d_in[14];
    const float* g1_s1  = (const float*)d_in[15];
    const float* b1_s1  = (const float*)d_in[16];
    const float* Wf     = (const float*)d_in[17];
    const float* gf     = (const float*)d_in[18];
    const float* bf     = (const float*)d_in[19];
    (void)in_sizes; (void)n_in; (void)out_size;

    void* zrp; cudaGetSymbolAddress(&zrp, g_zr);
    cudaMemsetAsync(zrp, 0, (512 + 2 * NCELL) * sizeof(float));

    k_scatter<<<128, 256>>>(pxyz);
    k_group2<<<4608, 256>>>(kp, pxyz, pfeat, sf, stridep);

    k_mlp2<<<512, 256>>>(W0_s0, g0_s0, b0_s0, W1_s0, W0_s1, g0_s1, b0_s1, W1_s1);
    k_poolmm<<<768, 256>>>(g1_s0, b1_s0, g1_s1, b1_s1);

    k_fgemm<<<128, 256>>>(Wf);
    k_fbn<<<512, 256>>>(gf, bf, (float*)d_out);
}